// round 7
// baseline (speedup 1.0000x reference)
#include <cuda_runtime.h>
#include <cuda_bf16.h>
#include <cfloat>

// Problem constants
constexpr int L   = 8192;   // row length
constexpr int NB  = 65;     // bins / quantile edges
constexpr int NT  = 512;    // threads per block
constexpr int IPT = 16;     // items per thread (NT*IPT == L)
constexpr int RUN = 512;    // per-warp sorted run (32 lanes * 16 items)

// Shared layout: bufA[8192] | bufB[8192] | hist[NB*NB]
constexpr size_t BUF_BYTES  = (size_t)L * sizeof(float);
constexpr size_t SMEM_TOTAL = 2 * BUF_BYTES + (size_t)NB * NB * sizeof(unsigned);

// ---------------- bitonic helpers (warp sorts 512 elems, 16/thread) ----------
template <int J>
__device__ __forceinline__ void inthread_stage(float (&v)[IPT], int k, int lane)
{
#pragma unroll
    for (int i = 0; i < IPT; ++i) {
        if ((i & J) != 0) continue;          // compile-time
        const int q = i | J;
        const int p = (lane << 4) | i;       // index within 512-run
        const bool asc = ((p & k) == 0);
        float a = v[i], b = v[q];
        float mn = fminf(a, b), mx = fmaxf(a, b);
        v[i] = asc ? mn : mx;
        v[q] = asc ? mx : mn;
    }
}

__device__ __forceinline__ void cross_stage(float (&v)[IPT], int k, int j, int lane)
{
    const int  lmask = j >> 4;               // lane xor distance
    const bool up    = (lane & lmask) == 0;  // we are the lower partner
#pragma unroll
    for (int i = 0; i < IPT; ++i) {
        const int p = (lane << 4) | i;
        const bool asc = ((p & k) == 0);     // uniform per thread for k>=16
        float other = __shfl_xor_sync(0xffffffffu, v[i], lmask);
        const bool keepMin = (asc == up);
        v[i] = keepMin ? fminf(v[i], other) : fmaxf(v[i], other);
    }
}

__device__ __forceinline__ void warp_bitonic_512(float (&v)[IPT], int lane)
{
    for (int k = 2; k <= RUN; k <<= 1) {
        for (int j = k >> 1; j >= 16; j >>= 1)
            cross_stage(v, k, j, lane);
        if (k >= 16) {
            inthread_stage<8>(v, k, lane);
            inthread_stage<4>(v, k, lane);
            inthread_stage<2>(v, k, lane);
            inthread_stage<1>(v, k, lane);
        } else if (k == 8) {
            inthread_stage<4>(v, k, lane);
            inthread_stage<2>(v, k, lane);
            inthread_stage<1>(v, k, lane);
        } else if (k == 4) {
            inthread_stage<2>(v, k, lane);
            inthread_stage<1>(v, k, lane);
        } else {  // k == 2
            inthread_stage<1>(v, k, lane);
        }
    }
}

// ---------------- merge-path round: runs of length R -> 2R --------------------
template <int R>
__device__ __forceinline__ void merge_round(const float* __restrict__ src,
                                            float* __restrict__ dst, int t)
{
    const int seg0    = t << 4;              // 16 outputs per thread
    const int pairlen = R << 1;
    const int pair    = seg0 / pairlen;      // compile-time shift
    const int o       = seg0 & (pairlen - 1);
    const float* __restrict__ A = src + pair * pairlen;
    const float* __restrict__ B = A + R;

    // merge-path partition (A takes ties)
    int alo = o - R; if (alo < 0) alo = 0;
    int ahi = (o < R) ? o : R;
    while (alo < ahi) {
        int amid = (alo + ahi) >> 1;
        if (A[amid] <= B[o - 1 - amid]) alo = amid + 1; else ahi = amid;
    }
    int a = alo, b = o - alo;

    float av = (a < R) ? A[a] : FLT_MAX;
    float bv = (b < R) ? B[b] : FLT_MAX;
    float* __restrict__ outp = dst + pair * pairlen + o;
#pragma unroll
    for (int i = 0; i < IPT; ++i) {
        bool takeA = (a < R) && (b >= R || av <= bv);
        float ov = takeA ? av : bv;
        if (takeA) { ++a; av = (a < R) ? A[a] : FLT_MAX; }
        else       { ++b; bv = (b < R) ? B[b] : FLT_MAX; }
        outp[i] = ov;
    }
}

// k-th smallest (0-indexed) of the union of two sorted ascending arrays A[n], B[n].
__device__ __forceinline__ float select2(const float* __restrict__ A,
                                         const float* __restrict__ B,
                                         int n, int k)
{
    int ilo = (k + 1 - n > 0) ? (k + 1 - n) : 0;
    int ihi = (k + 1 < n) ? (k + 1) : n;
    for (;;) {
        int i = (ilo + ihi) >> 1;   // take i from A, j from B
        int j = k + 1 - i;
        float Aim1 = (i > 0) ? A[i - 1] : -FLT_MAX;
        float Ai   = (i < n) ? A[i]     :  FLT_MAX;
        float Bjm1 = (j > 0) ? B[j - 1] : -FLT_MAX;
        float Bj   = (j < n) ? B[j]     :  FLT_MAX;
        if (Aim1 > Bj)       ihi = i - 1;
        else if (Bjm1 > Ai)  ilo = i + 1;
        else return fmaxf(Aim1, Bjm1);
    }
}

__global__ __launch_bounds__(NT, 2) void mtf_kernel(const float* __restrict__ x,
                                                    float* __restrict__ out,
                                                    int rows)
{
    extern __shared__ char smem_raw[];
    float*    bufA = reinterpret_cast<float*>(smem_raw);
    float*    bufB = reinterpret_cast<float*>(smem_raw + BUF_BYTES);
    unsigned* hist = reinterpret_cast<unsigned*>(smem_raw + 2 * BUF_BYTES);

    __shared__ float s_eytz[128];    // BFS layout of 127 padded edges
    __shared__ int   s_wmin[16], s_wmax[16], s_wneg[16];
    __shared__ int   s_m, s_neg;
    __shared__ unsigned char s_firstbin[NT];

    const int t    = threadIdx.x;
    const int w    = t >> 5;
    const int lane = t & 31;
    const float inv = 1.0f / (float)(L - 1);

    int prev = -1;   // row whose histogram is pending writeout

    for (int row = blockIdx.x; row < rows; row += gridDim.x) {
        const float4* __restrict__ xr4 =
            reinterpret_cast<const float4*>(x + (size_t)row * L);

        // ---- Phase 1: load raw row, per-thread scan (registers only) ----
        float v[IPT];
        int lmin = L, lmax = -1, lneg = 0;
#pragma unroll
        for (int j = 0; j < 4; ++j) {
            float4 p = xr4[t * 4 + j];
            int base = t * IPT + j * 4;
            v[j * 4 + 0] = p.x; v[j * 4 + 1] = p.y;
            v[j * 4 + 2] = p.z; v[j * 4 + 3] = p.w;
#pragma unroll
            for (int c = 0; c < 4; ++c) {
                float val = v[j * 4 + c];
                int idx = base + c;
                if (val != 0.0f) { if (idx < lmin) lmin = idx; if (idx > lmax) lmax = idx; }
                lneg += (val < 0.0f) ? 1 : 0;
            }
        }
        // warp-level reductions; leaders stash per-warp partials
        lmin = __reduce_min_sync(0xffffffffu, lmin);
        lmax = __reduce_max_sync(0xffffffffu, lmax);
        lneg = __reduce_add_sync(0xffffffffu, lneg);
        if (lane == 0) { s_wmin[w] = lmin; s_wmax[w] = lmax; s_wneg[w] = lneg; }

        // ---- Phase 2: bitonic sort RAW values (ALU/SHFL only).
        // This overlaps the still-draining histogram atomics of row `prev`.
        warp_bitonic_512(v, lane);
#pragma unroll
        for (int i = 0; i < IPT; ++i) bufA[t * IPT + i] = v[i];

        __syncthreads();   // SYNC A: drains prev-row atomics; publishes s_w*, runs

        // ---- Phase 3: (warp 0) finalize scan; (warps 1-15) writeout prev + zero ----
        if (w == 0) {
            if (lane < 16) {
                int a = s_wmin[lane], b = s_wmax[lane], c = s_wneg[lane];
                a = __reduce_min_sync(0x0000ffffu, a);
                b = __reduce_max_sync(0x0000ffffu, b);
                c = __reduce_add_sync(0x0000ffffu, c);
                if (lane == 0) {
                    s_m   = (b >= 0) ? (b - a + 1) : 0;
                    s_neg = c;
                }
            }
        } else {
            if (prev >= 0) {
                float* __restrict__ op = out + (size_t)prev * NB * NB;
                for (int i = t - 32; i < NB * NB; i += NT - 32) {
                    op[i] = (float)hist[i] * inv;
                    hist[i] = 0u;
                }
            } else {
                for (int i = t - 32; i < NB * NB; i += NT - 32) hist[i] = 0u;
            }
        }
        __syncthreads();   // SYNC B

        // ---- Phase 4: three merge rounds: 512 -> 1024 -> 2048 -> 4096 ----
        merge_round<512>(bufA, bufB, t);  __syncthreads();
        merge_round<1024>(bufB, bufA, t); __syncthreads();
        merge_round<2048>(bufA, bufB, t); __syncthreads();
        // two sorted runs of 4096 in bufB[0..4096) and bufB[4096..8192)

        // ---- Phase 5: Eytzinger nodes select their edge directly.
        // masked[k] = raw[k] if k < neg_count else raw[k + z_out]  (z_out = L - m)
        if (t >= 1 && t < 128) {
            int d    = 31 - __clz((unsigned)t);
            int idx0 = ((((t - (1 << d)) << 1) + 1) << (6 - d)) - 1;   // in-order index
            float q = FLT_MAX;
            if (idx0 < NB) {
                int m = s_m;
                if (m > 0) {
                    const float step = 1.0f / 65.0f;
                    float qlev = (float)idx0 * step;
                    float pos  = qlev * (float)(m - 1);
                    int   lo   = (int)floorf(pos);
                    int   hi   = (int)ceilf(pos);
                    float frac = pos - (float)lo;
                    int neg = s_neg, zout = L - m;
                    int klo = (lo < neg) ? lo : lo + zout;
                    int khi = (hi < neg) ? hi : hi + zout;
                    float vlo = select2(bufB, bufB + 4096, 4096, klo);
                    float vhi = (khi == klo) ? vlo
                                             : select2(bufB, bufB + 4096, 4096, khi);
                    q = vlo + frac * (vhi - vlo);
                } else {
                    q = 0.0f;
                }
            }
            s_eytz[t] = q;
        }
        __syncthreads();

        // ---- Phase 6: bin every value via conflict-free Eytzinger search ----
        int binreg[IPT];
#pragma unroll
        for (int j = 0; j < 4; ++j) {
            float4 p = xr4[t * 4 + j];          // L1-hot reload
            float vals[4] = {p.x, p.y, p.z, p.w};
#pragma unroll
            for (int c = 0; c < 4; ++c) {
                float val = vals[c];
                unsigned node = 1;
#pragma unroll
                for (int s = 0; s < 7; ++s)
                    node = 2u * node + (s_eytz[node] <= val ? 1u : 0u);
                int b = (int)node - 128;        // count of edges <= val
                binreg[j * 4 + c] = (b > NB - 1) ? (NB - 1) : b;
            }
        }
        s_firstbin[t] = (unsigned char)binreg[0];
        __syncthreads();

        // ---- Phase 7: fire-and-forget transition atomics; NO trailing barrier.
        // They drain under the next row's load + bitonic.
#pragma unroll
        for (int i = 0; i < IPT - 1; ++i)
            atomicAdd(&hist[binreg[i] * NB + binreg[i + 1]], 1u);
        if (t < NT - 1)
            atomicAdd(&hist[binreg[IPT - 1] * NB + (int)s_firstbin[t + 1]], 1u);

        prev = row;
    }

    // ---- Epilogue: writeout the last row's histogram ----
    __syncthreads();
    if (prev >= 0) {
        float* __restrict__ op = out + (size_t)prev * NB * NB;
        for (int i = t; i < NB * NB; i += NT)
            op[i] = (float)hist[i] * inv;
    }
}

extern "C" void kernel_launch(void* const* d_in, const int* in_sizes, int n_in,
                              void* d_out, int out_size)
{
    const float* x = (const float*)d_in[0];
    float* out = (float*)d_out;
    const int rows = in_sizes[0] / L;   // 512*4 = 2048

    int grid = 296;                     // 2 CTAs/SM * 148 SMs (persistent)
    if (grid > rows) grid = rows;

    cudaFuncSetAttribute(mtf_kernel,
                         cudaFuncAttributeMaxDynamicSharedMemorySize,
                         (int)SMEM_TOTAL);
    mtf_kernel<<<grid, NT, SMEM_TOTAL>>>(x, out, rows);
}

// round 8
// speedup vs baseline: 1.1544x; 1.1544x over previous
#include <cuda_runtime.h>
#include <cuda_bf16.h>
#include <cfloat>

// Problem constants
constexpr int L   = 8192;   // row length
constexpr int NB  = 65;     // bins / quantile edges
constexpr int NT  = 512;    // threads per block
constexpr int IPT = 16;     // items per thread (NT*IPT == L)
constexpr int RUN = 512;    // per-warp sorted run (32 lanes * 16 items)

// Shared layout: bufA[8192] | bufB[8192] | hist[NB*NB]
constexpr size_t BUF_BYTES  = (size_t)L * sizeof(float);
constexpr size_t SMEM_TOTAL = 2 * BUF_BYTES + (size_t)NB * NB * sizeof(unsigned);

// ---------------- bitonic helpers (warp sorts 512 elems, 16/thread) ----------
template <int J>
__device__ __forceinline__ void inthread_stage(float (&v)[IPT], int k, int lane)
{
#pragma unroll
    for (int i = 0; i < IPT; ++i) {
        if ((i & J) != 0) continue;          // compile-time
        const int q = i | J;
        const int p = (lane << 4) | i;       // index within 512-run
        const bool asc = ((p & k) == 0);
        float a = v[i], b = v[q];
        float mn = fminf(a, b), mx = fmaxf(a, b);
        v[i] = asc ? mn : mx;
        v[q] = asc ? mx : mn;
    }
}

__device__ __forceinline__ void cross_stage(float (&v)[IPT], int k, int j, int lane)
{
    const int  lmask = j >> 4;               // lane xor distance
    const bool up    = (lane & lmask) == 0;  // we are the lower partner
#pragma unroll
    for (int i = 0; i < IPT; ++i) {
        const int p = (lane << 4) | i;
        const bool asc = ((p & k) == 0);     // uniform per thread for k>=16
        float other = __shfl_xor_sync(0xffffffffu, v[i], lmask);
        const bool keepMin = (asc == up);
        v[i] = keepMin ? fminf(v[i], other) : fmaxf(v[i], other);
    }
}

__device__ __forceinline__ void warp_bitonic_512(float (&v)[IPT], int lane)
{
    for (int k = 2; k <= RUN; k <<= 1) {
        for (int j = k >> 1; j >= 16; j >>= 1)
            cross_stage(v, k, j, lane);
        if (k >= 16) {
            inthread_stage<8>(v, k, lane);
            inthread_stage<4>(v, k, lane);
            inthread_stage<2>(v, k, lane);
            inthread_stage<1>(v, k, lane);
        } else if (k == 8) {
            inthread_stage<4>(v, k, lane);
            inthread_stage<2>(v, k, lane);
            inthread_stage<1>(v, k, lane);
        } else if (k == 4) {
            inthread_stage<2>(v, k, lane);
            inthread_stage<1>(v, k, lane);
        } else {  // k == 2
            inthread_stage<1>(v, k, lane);
        }
    }
}

// ---------------- merge-path round: runs of length R -> 2R --------------------
template <int R>
__device__ __forceinline__ void merge_round(const float* __restrict__ src,
                                            float* __restrict__ dst, int t)
{
    const int seg0    = t << 4;              // 16 outputs per thread
    const int pairlen = R << 1;
    const int pair    = seg0 / pairlen;      // compile-time shift
    const int o       = seg0 & (pairlen - 1);
    const float* __restrict__ A = src + pair * pairlen;
    const float* __restrict__ B = A + R;

    // merge-path partition (A takes ties)
    int alo = o - R; if (alo < 0) alo = 0;
    int ahi = (o < R) ? o : R;
    while (alo < ahi) {
        int amid = (alo + ahi) >> 1;
        if (A[amid] <= B[o - 1 - amid]) alo = amid + 1; else ahi = amid;
    }
    int a = alo, b = o - alo;

    float av = (a < R) ? A[a] : FLT_MAX;
    float bv = (b < R) ? B[b] : FLT_MAX;
    float* __restrict__ outp = dst + pair * pairlen + o;
#pragma unroll
    for (int i = 0; i < IPT; ++i) {
        bool takeA = (a < R) && (b >= R || av <= bv);
        float ov = takeA ? av : bv;
        if (takeA) { ++a; av = (a < R) ? A[a] : FLT_MAX; }
        else       { ++b; bv = (b < R) ? B[b] : FLT_MAX; }
        outp[i] = ov;
    }
}

// k-th smallest (0-indexed) of the union of two sorted ascending arrays A[n], B[n].
__device__ __forceinline__ float select2(const float* __restrict__ A,
                                         const float* __restrict__ B,
                                         int n, int k)
{
    int ilo = (k + 1 - n > 0) ? (k + 1 - n) : 0;
    int ihi = (k + 1 < n) ? (k + 1) : n;
    for (;;) {
        int i = (ilo + ihi) >> 1;   // take i from A, j from B
        int j = k + 1 - i;
        float Aim1 = (i > 0) ? A[i - 1] : -FLT_MAX;
        float Ai   = (i < n) ? A[i]     :  FLT_MAX;
        float Bjm1 = (j > 0) ? B[j - 1] : -FLT_MAX;
        float Bj   = (j < n) ? B[j]     :  FLT_MAX;
        if (Aim1 > Bj)       ihi = i - 1;
        else if (Bjm1 > Ai)  ilo = i + 1;
        else return fmaxf(Aim1, Bjm1);
    }
}

__global__ __launch_bounds__(NT, 2) void mtf_kernel(const float* __restrict__ x,
                                                    float* __restrict__ out)
{
    extern __shared__ char smem_raw[];
    float*    bufA = reinterpret_cast<float*>(smem_raw);
    float*    bufB = reinterpret_cast<float*>(smem_raw + BUF_BYTES);
    unsigned* hist = reinterpret_cast<unsigned*>(smem_raw + 2 * BUF_BYTES);

    __shared__ float s_eytz[128];    // BFS layout of 127 padded edges
    __shared__ int   s_wmin[16], s_wmax[16], s_wneg[16];
    __shared__ int   s_m, s_neg;

    const int row  = blockIdx.x;
    const int t    = threadIdx.x;
    const int w    = t >> 5;
    const int lane = t & 31;

    const float* __restrict__ xr = x + (size_t)row * L;
    const float4* __restrict__ xr4 = reinterpret_cast<const float4*>(xr);

    // ---- Phase 1: load raw row, per-thread scan (registers only) ----
    float v[IPT];
    int lmin = L, lmax = -1, lneg = 0;
#pragma unroll
    for (int j = 0; j < 4; ++j) {
        float4 p = xr4[t * 4 + j];
        int base = t * IPT + j * 4;
        v[j * 4 + 0] = p.x; v[j * 4 + 1] = p.y;
        v[j * 4 + 2] = p.z; v[j * 4 + 3] = p.w;
#pragma unroll
        for (int c = 0; c < 4; ++c) {
            float val = v[j * 4 + c];
            int idx = base + c;
            if (val != 0.0f) { if (idx < lmin) lmin = idx; if (idx > lmax) lmax = idx; }
            lneg += (val < 0.0f) ? 1 : 0;
        }
    }
    lmin = __reduce_min_sync(0xffffffffu, lmin);
    lmax = __reduce_max_sync(0xffffffffu, lmax);
    lneg = __reduce_add_sync(0xffffffffu, lneg);
    if (lane == 0) { s_wmin[w] = lmin; s_wmax[w] = lmax; s_wneg[w] = lneg; }

    // ---- Phase 2: bitonic sort RAW values (ALU/SHFL only, no mask pass) ----
    warp_bitonic_512(v, lane);
#pragma unroll
    for (int i = 0; i < IPT; ++i) bufA[t * IPT + i] = v[i];

    // hist zeroing in the shadow before the barrier
    for (int i = t; i < NB * NB; i += NT) hist[i] = 0u;

    __syncthreads();                             // SYNC 1

    // ---- Phase 3: warp 0 finalizes the scan while everyone merges ----
    if (w == 0 && lane < 16) {
        int a = s_wmin[lane], b = s_wmax[lane], c = s_wneg[lane];
        a = __reduce_min_sync(0x0000ffffu, a);
        b = __reduce_max_sync(0x0000ffffu, b);
        c = __reduce_add_sync(0x0000ffffu, c);
        if (lane == 0) {
            s_m   = (b >= 0) ? (b - s_wmin[0] * 0 - a + 1) : 0;   // m = last-first+1
            s_neg = c;
        }
    }

    // ---- Phase 4: three merge rounds: 512 -> 1024 -> 2048 -> 4096 ----
    merge_round<512>(bufA, bufB, t);  __syncthreads();   // SYNC 2
    merge_round<1024>(bufB, bufA, t); __syncthreads();   // SYNC 3
    merge_round<2048>(bufA, bufB, t); __syncthreads();   // SYNC 4
    // two sorted runs of 4096 in bufB[0..4096) and bufB[4096..8192)

    // ---- Phase 5: Eytzinger nodes select their edge directly.
    // masked[k] = raw_sorted[k] if k < neg_count else raw_sorted[k + zout]
    if (t >= 1 && t < 128) {
        int d    = 31 - __clz((unsigned)t);
        int idx0 = ((((t - (1 << d)) << 1) + 1) << (6 - d)) - 1;   // in-order index
        float q = FLT_MAX;
        if (idx0 < NB) {
            int m = s_m;
            if (m > 0) {
                const float step = 1.0f / 65.0f;
                float qlev = (float)idx0 * step;
                float pos  = qlev * (float)(m - 1);
                int   lo   = (int)floorf(pos);
                int   hi   = (int)ceilf(pos);
                float frac = pos - (float)lo;
                int neg = s_neg, zout = L - m;
                int klo = (lo < neg) ? lo : lo + zout;
                int khi = (hi < neg) ? hi : hi + zout;
                float vlo = select2(bufB, bufB + 4096, 4096, klo);
                float vhi = (khi == klo) ? vlo
                                         : select2(bufB, bufB + 4096, 4096, khi);
                q = vlo + frac * (vhi - vlo);
            } else {
                q = 0.0f;
            }
        }
        s_eytz[t] = q;
    }
    __syncthreads();                             // SYNC 5

    // ---- Phase 6: bin all values (conflict-free Eytzinger, L1-hot reload) ----
    int binreg[IPT];
#pragma unroll
    for (int j = 0; j < 4; ++j) {
        float4 p = xr4[t * 4 + j];
        float vals[4] = {p.x, p.y, p.z, p.w};
#pragma unroll
        for (int c = 0; c < 4; ++c) {
            float val = vals[c];
            unsigned node = 1;
#pragma unroll
            for (int s = 0; s < 7; ++s)
                node = 2u * node + (s_eytz[node] <= val ? 1u : 0u);
            int b = (int)node - 128;             // count of edges <= val
            binreg[j * 4 + c] = (b > NB - 1) ? (NB - 1) : b;
        }
    }

    // boundary bin (next thread's first element) without smem/barrier:
    // lanes 0-30 get it by shuffle; lane 31 computes it directly.
    int nextbin = __shfl_down_sync(0xffffffffu, binreg[0], 1);
    if (lane == 31 && t < NT - 1) {
        float val = xr[t * IPT + IPT];           // L1-hot scalar load
        unsigned node = 1;
#pragma unroll
        for (int s = 0; s < 7; ++s)
            node = 2u * node + (s_eytz[node] <= val ? 1u : 0u);
        int b = (int)node - 128;
        nextbin = (b > NB - 1) ? (NB - 1) : b;
    }

    // ---- Phase 7: transition histogram (shared atomics) ----
#pragma unroll
    for (int i = 0; i < IPT - 1; ++i)
        atomicAdd(&hist[binreg[i] * NB + binreg[i + 1]], 1u);
    if (t < NT - 1)
        atomicAdd(&hist[binreg[IPT - 1] * NB + nextbin], 1u);
    __syncthreads();                             // SYNC 6

    // ---- Phase 8: normalize + store ----
    const float inv = 1.0f / (float)(L - 1);
    float* __restrict__ outr = out + (size_t)row * NB * NB;
    for (int i = t; i < NB * NB; i += NT)
        outr[i] = (float)hist[i] * inv;
}

extern "C" void kernel_launch(void* const* d_in, const int* in_sizes, int n_in,
                              void* d_out, int out_size)
{
    const float* x = (const float*)d_in[0];
    float* out = (float*)d_out;
    const int rows = in_sizes[0] / L;   // 512*4 = 2048

    cudaFuncSetAttribute(mtf_kernel,
                         cudaFuncAttributeMaxDynamicSharedMemorySize,
                         (int)SMEM_TOTAL);
    mtf_kernel<<<rows, NT, SMEM_TOTAL>>>(x, out);
}

// round 9
// speedup vs baseline: 1.2360x; 1.0707x over previous
#include <cuda_runtime.h>
#include <cuda_bf16.h>
#include <cfloat>

// Problem constants
constexpr int L   = 8192;   // row length
constexpr int NB  = 65;     // bins / quantile edges
constexpr int NT  = 512;    // threads per block
constexpr int IPT = 16;     // items per thread (NT*IPT == L)
constexpr int RUN = 512;    // per-warp sorted run (32 lanes * 16 items)

// Skewed (padded) addressing: one pad float per 32 -> stride-16 warp accesses
// land on 32 distinct banks instead of 2.
__device__ __forceinline__ int PAD(int i) { return i + (i >> 5); }
constexpr int PADL = L + (L >> 5);          // 8448 floats per buffer

// Shared layout: bufA[PADL] | bufB[PADL] | hist[NB*NB]
constexpr size_t BUF_BYTES  = (size_t)PADL * sizeof(float);
constexpr size_t SMEM_TOTAL = 2 * BUF_BYTES + (size_t)NB * NB * sizeof(unsigned);

// ---------------- bitonic helpers (warp sorts 512 elems, 16/thread) ----------
template <int J>
__device__ __forceinline__ void inthread_stage(float (&v)[IPT], int k, int lane)
{
#pragma unroll
    for (int i = 0; i < IPT; ++i) {
        if ((i & J) != 0) continue;          // compile-time
        const int q = i | J;
        const int p = (lane << 4) | i;       // index within 512-run
        const bool asc = ((p & k) == 0);
        float a = v[i], b = v[q];
        float mn = fminf(a, b), mx = fmaxf(a, b);
        v[i] = asc ? mn : mx;
        v[q] = asc ? mx : mn;
    }
}

__device__ __forceinline__ void cross_stage(float (&v)[IPT], int k, int j, int lane)
{
    const int  lmask = j >> 4;               // lane xor distance
    const bool up    = (lane & lmask) == 0;  // we are the lower partner
#pragma unroll
    for (int i = 0; i < IPT; ++i) {
        const int p = (lane << 4) | i;
        const bool asc = ((p & k) == 0);     // uniform per thread for k>=16
        float other = __shfl_xor_sync(0xffffffffu, v[i], lmask);
        const bool keepMin = (asc == up);
        v[i] = keepMin ? fminf(v[i], other) : fmaxf(v[i], other);
    }
}

__device__ __forceinline__ void warp_bitonic_512(float (&v)[IPT], int lane)
{
    for (int k = 2; k <= RUN; k <<= 1) {
        for (int j = k >> 1; j >= 16; j >>= 1)
            cross_stage(v, k, j, lane);
        if (k >= 16) {
            inthread_stage<8>(v, k, lane);
            inthread_stage<4>(v, k, lane);
            inthread_stage<2>(v, k, lane);
            inthread_stage<1>(v, k, lane);
        } else if (k == 8) {
            inthread_stage<4>(v, k, lane);
            inthread_stage<2>(v, k, lane);
            inthread_stage<1>(v, k, lane);
        } else if (k == 4) {
            inthread_stage<2>(v, k, lane);
            inthread_stage<1>(v, k, lane);
        } else {  // k == 2
            inthread_stage<1>(v, k, lane);
        }
    }
}

// ---------------- merge-path round: runs of length R -> 2R (padded bufs) -----
template <int R>
__device__ __forceinline__ void merge_round(const float* __restrict__ src,
                                            float* __restrict__ dst, int t)
{
    const int seg0    = t << 4;              // 16 outputs per thread
    const int pairlen = R << 1;
    const int pairbase = (seg0 / pairlen) * pairlen;   // compile-time shifts
    const int o       = seg0 & (pairlen - 1);
    const int Abase   = pairbase;
    const int Bbase   = pairbase + R;

    // merge-path partition (A takes ties)
    int alo = o - R; if (alo < 0) alo = 0;
    int ahi = (o < R) ? o : R;
    while (alo < ahi) {
        int amid = (alo + ahi) >> 1;
        if (src[PAD(Abase + amid)] <= src[PAD(Bbase + o - 1 - amid)]) alo = amid + 1;
        else ahi = amid;
    }
    int a = alo, b = o - alo;

    float av = (a < R) ? src[PAD(Abase + a)] : FLT_MAX;
    float bv = (b < R) ? src[PAD(Bbase + b)] : FLT_MAX;
    const int outbase = pairbase + o;
#pragma unroll
    for (int i = 0; i < IPT; ++i) {
        bool takeA = (a < R) && (b >= R || av <= bv);
        float ov = takeA ? av : bv;
        if (takeA) { ++a; av = (a < R) ? src[PAD(Abase + a)] : FLT_MAX; }
        else       { ++b; bv = (b < R) ? src[PAD(Bbase + b)] : FLT_MAX; }
        dst[PAD(outbase + i)] = ov;
    }
}

// k-th smallest (0-indexed) of the union of two sorted runs living in the SAME
// padded buffer at index bases Ab and Bb, each of length n.
__device__ __forceinline__ float select2(const float* __restrict__ buf,
                                         int Ab, int Bb, int n, int k)
{
    int ilo = (k + 1 - n > 0) ? (k + 1 - n) : 0;
    int ihi = (k + 1 < n) ? (k + 1) : n;
    for (;;) {
        int i = (ilo + ihi) >> 1;   // take i from A, j from B
        int j = k + 1 - i;
        float Aim1 = (i > 0) ? buf[PAD(Ab + i - 1)] : -FLT_MAX;
        float Ai   = (i < n) ? buf[PAD(Ab + i)]     :  FLT_MAX;
        float Bjm1 = (j > 0) ? buf[PAD(Bb + j - 1)] : -FLT_MAX;
        float Bj   = (j < n) ? buf[PAD(Bb + j)]     :  FLT_MAX;
        if (Aim1 > Bj)       ihi = i - 1;
        else if (Bjm1 > Ai)  ilo = i + 1;
        else return fmaxf(Aim1, Bjm1);
    }
}

__global__ __launch_bounds__(NT, 2) void mtf_kernel(const float* __restrict__ x,
                                                    float* __restrict__ out)
{
    extern __shared__ char smem_raw[];
    float*    bufA = reinterpret_cast<float*>(smem_raw);
    float*    bufB = reinterpret_cast<float*>(smem_raw + BUF_BYTES);
    unsigned* hist = reinterpret_cast<unsigned*>(smem_raw + 2 * BUF_BYTES);

    __shared__ float s_eytz[128];    // BFS layout of 127 padded edges
    __shared__ int   s_wmin[16], s_wmax[16], s_wneg[16];
    __shared__ int   s_m, s_neg;

    const int row  = blockIdx.x;
    const int t    = threadIdx.x;
    const int w    = t >> 5;
    const int lane = t & 31;

    const float* __restrict__ xr = x + (size_t)row * L;
    const float4* __restrict__ xr4 = reinterpret_cast<const float4*>(xr);

    // ---- Phase 1: load raw row, per-thread scan (registers only) ----
    float v[IPT];
    int lmin = L, lmax = -1, lneg = 0;
#pragma unroll
    for (int j = 0; j < 4; ++j) {
        float4 p = xr4[t * 4 + j];
        int base = t * IPT + j * 4;
        v[j * 4 + 0] = p.x; v[j * 4 + 1] = p.y;
        v[j * 4 + 2] = p.z; v[j * 4 + 3] = p.w;
#pragma unroll
        for (int c = 0; c < 4; ++c) {
            float val = v[j * 4 + c];
            int idx = base + c;
            if (val != 0.0f) { if (idx < lmin) lmin = idx; if (idx > lmax) lmax = idx; }
            lneg += (val < 0.0f) ? 1 : 0;
        }
    }
    lmin = __reduce_min_sync(0xffffffffu, lmin);
    lmax = __reduce_max_sync(0xffffffffu, lmax);
    lneg = __reduce_add_sync(0xffffffffu, lneg);
    if (lane == 0) { s_wmin[w] = lmin; s_wmax[w] = lmax; s_wneg[w] = lneg; }

    // ---- Phase 2: bitonic sort RAW values (ALU/SHFL only, no mask pass) ----
    warp_bitonic_512(v, lane);
#pragma unroll
    for (int i = 0; i < IPT; ++i) bufA[PAD(t * IPT + i)] = v[i];   // conflict-free

    // hist zeroing in the shadow before the barrier
    for (int i = t; i < NB * NB; i += NT) hist[i] = 0u;

    __syncthreads();                             // SYNC 1

    // ---- Phase 3: warp 0 finalizes the scan while everyone merges ----
    if (w == 0 && lane < 16) {
        int a = s_wmin[lane], b = s_wmax[lane], c = s_wneg[lane];
        a = __reduce_min_sync(0x0000ffffu, a);
        b = __reduce_max_sync(0x0000ffffu, b);
        c = __reduce_add_sync(0x0000ffffu, c);
        if (lane == 0) {
            s_m   = (b >= 0) ? (b - a + 1) : 0;
            s_neg = c;
        }
    }

    // ---- Phase 4: three merge rounds: 512 -> 1024 -> 2048 -> 4096 ----
    merge_round<512>(bufA, bufB, t);  __syncthreads();   // SYNC 2
    merge_round<1024>(bufB, bufA, t); __syncthreads();   // SYNC 3
    merge_round<2048>(bufA, bufB, t); __syncthreads();   // SYNC 4
    // two sorted runs of 4096 at padded bases 0 and 4096 in bufB

    // ---- Phase 5: Eytzinger nodes select their edge directly.
    // masked[k] = raw_sorted[k] if k < neg_count else raw_sorted[k + zout]
    if (t >= 1 && t < 128) {
        int d    = 31 - __clz((unsigned)t);
        int idx0 = ((((t - (1 << d)) << 1) + 1) << (6 - d)) - 1;   // in-order index
        float q = FLT_MAX;
        if (idx0 < NB) {
            int m = s_m;
            if (m > 0) {
                const float step = 1.0f / 65.0f;
                float qlev = (float)idx0 * step;
                float pos  = qlev * (float)(m - 1);
                int   lo   = (int)floorf(pos);
                int   hi   = (int)ceilf(pos);
                float frac = pos - (float)lo;
                int neg = s_neg, zout = L - m;
                int klo = (lo < neg) ? lo : lo + zout;
                int khi = (hi < neg) ? hi : hi + zout;
                float vlo = select2(bufB, 0, 4096, 4096, klo);
                float vhi = (khi == klo) ? vlo
                                         : select2(bufB, 0, 4096, 4096, khi);
                q = vlo + frac * (vhi - vlo);
            } else {
                q = 0.0f;
            }
        }
        s_eytz[t] = q;
    }
    __syncthreads();                             // SYNC 5

    // ---- Phase 6: bin all values (conflict-free Eytzinger, L1-hot reload) ----
    int binreg[IPT];
#pragma unroll
    for (int j = 0; j < 4; ++j) {
        float4 p = xr4[t * 4 + j];
        float vals[4] = {p.x, p.y, p.z, p.w};
#pragma unroll
        for (int c = 0; c < 4; ++c) {
            float val = vals[c];
            unsigned node = 1;
#pragma unroll
            for (int s = 0; s < 7; ++s)
                node = 2u * node + (s_eytz[node] <= val ? 1u : 0u);
            int b = (int)node - 128;             // count of edges <= val
            binreg[j * 4 + c] = (b > NB - 1) ? (NB - 1) : b;
        }
    }

    // boundary bin (next thread's first element) without smem/barrier:
    // lanes 0-30 get it by shuffle; lane 31 computes it directly.
    int nextbin = __shfl_down_sync(0xffffffffu, binreg[0], 1);
    if (lane == 31 && t < NT - 1) {
        float val = xr[t * IPT + IPT];           // L1-hot scalar load
        unsigned node = 1;
#pragma unroll
        for (int s = 0; s < 7; ++s)
            node = 2u * node + (s_eytz[node] <= val ? 1u : 0u);
        int b = (int)node - 128;
        nextbin = (b > NB - 1) ? (NB - 1) : b;
    }

    // ---- Phase 7: transition histogram (shared atomics) ----
#pragma unroll
    for (int i = 0; i < IPT - 1; ++i)
        atomicAdd(&hist[binreg[i] * NB + binreg[i + 1]], 1u);
    if (t < NT - 1)
        atomicAdd(&hist[binreg[IPT - 1] * NB + nextbin], 1u);
    __syncthreads();                             // SYNC 6

    // ---- Phase 8: normalize + store ----
    const float inv = 1.0f / (float)(L - 1);
    float* __restrict__ outr = out + (size_t)row * NB * NB;
    for (int i = t; i < NB * NB; i += NT)
        outr[i] = (float)hist[i] * inv;
}

extern "C" void kernel_launch(void* const* d_in, const int* in_sizes, int n_in,
                              void* d_out, int out_size)
{
    const float* x = (const float*)d_in[0];
    float* out = (float*)d_out;
    const int rows = in_sizes[0] / L;   // 512*4 = 2048

    cudaFuncSetAttribute(mtf_kernel,
                         cudaFuncAttributeMaxDynamicSharedMemorySize,
                         (int)SMEM_TOTAL);
    mtf_kernel<<<rows, NT, SMEM_TOTAL>>>(x, out);
}

// round 10
// speedup vs baseline: 1.3983x; 1.1313x over previous
#include <cuda_runtime.h>
#include <cuda_bf16.h>
#include <cfloat>

// Problem constants
constexpr int L   = 8192;   // row length
constexpr int NB  = 65;     // bins / quantile edges
constexpr int NT  = 512;    // threads per block
constexpr int IPT = 16;     // items per thread (NT*IPT == L)

// Skewed (padded) addressing: one pad float per 32 -> strided warp accesses
// land on 32 distinct banks instead of few.
__device__ __forceinline__ int PAD(int i) { return i + (i >> 5); }
constexpr int PADL = L + (L >> 5);          // 8448 floats per buffer

// Shared layout: bufA[PADL] | bufB[PADL] | hist[NB*NB]
constexpr size_t BUF_BYTES  = (size_t)PADL * sizeof(float);
constexpr size_t SMEM_TOTAL = 2 * BUF_BYTES + (size_t)NB * NB * sizeof(unsigned);

// ---------------- bitonic (warp sorts 512, 16/thread), templated stages ------
// Direction of a CE at sort-stage K for element p = (lane<<4)|i:
//   asc = ((p & K) == 0).  For K>=32 this depends only on lane; for K==16 on
//   lane bit0; for K<=8 it is compile-time per item.

template <int K, int J>
__device__ __forceinline__ void cross_stage_t(float (&v)[IPT], int lane)
{
    const int  lmask   = J >> 4;
    const bool up      = (lane & lmask) == 0;
    const bool asc     = ((lane << 4) & K) == 0;       // hoisted (K>=32)
    const bool keepMin = (asc == up);
#pragma unroll
    for (int i = 0; i < IPT; ++i) {
        float other = __shfl_xor_sync(0xffffffffu, v[i], lmask);
        v[i] = keepMin ? fminf(v[i], other) : fmaxf(v[i], other);
    }
}

template <int K, int J>
__device__ __forceinline__ void inthread_stage_t(float (&v)[IPT], int lane)
{
    bool ascL = true;
    if constexpr (K >= 32)      ascL = (((lane << 4) & K) == 0);
    else if constexpr (K == 16) ascL = ((lane & 1) == 0);
#pragma unroll
    for (int i = 0; i < IPT; ++i) {
        if ((i & J) != 0) continue;                    // compile-time
        const int q = i | J;
        bool asc;
        if constexpr (K <= 8) asc = ((i & K) == 0);    // compile-time
        else                  asc = ascL;              // per-stage predicate
        float a = v[i], b = v[q];
        float mn = fminf(a, b), mx = fmaxf(a, b);
        v[i] = asc ? mn : mx;
        v[q] = asc ? mx : mn;
    }
}

template <int K>
__device__ __forceinline__ void inthread_tail(float (&v)[IPT], int lane)
{
    if constexpr (K >= 16) inthread_stage_t<K, 8>(v, lane);
    if constexpr (K >= 8)  inthread_stage_t<K, 4>(v, lane);
    if constexpr (K >= 4)  inthread_stage_t<K, 2>(v, lane);
    inthread_stage_t<K, 1>(v, lane);
}

__device__ __forceinline__ void warp_bitonic_512(float (&v)[IPT], int lane)
{
    inthread_tail<2>(v, lane);
    inthread_tail<4>(v, lane);
    inthread_tail<8>(v, lane);
    inthread_tail<16>(v, lane);

    cross_stage_t<32, 16>(v, lane);   inthread_tail<32>(v, lane);
    cross_stage_t<64, 32>(v, lane);
    cross_stage_t<64, 16>(v, lane);   inthread_tail<64>(v, lane);
    cross_stage_t<128, 64>(v, lane);
    cross_stage_t<128, 32>(v, lane);
    cross_stage_t<128, 16>(v, lane);  inthread_tail<128>(v, lane);
    cross_stage_t<256, 128>(v, lane);
    cross_stage_t<256, 64>(v, lane);
    cross_stage_t<256, 32>(v, lane);
    cross_stage_t<256, 16>(v, lane);  inthread_tail<256>(v, lane);
    cross_stage_t<512, 256>(v, lane);
    cross_stage_t<512, 128>(v, lane);
    cross_stage_t<512, 64>(v, lane);
    cross_stage_t<512, 32>(v, lane);
    cross_stage_t<512, 16>(v, lane);  inthread_tail<512>(v, lane);
}

// ------------- merge-path round, 2 independent 8-output chains per thread ----
template <int R>
__device__ __forceinline__ void merge_round(const float* __restrict__ src,
                                            float* __restrict__ dst, int t)
{
    const int pairlen = R << 1;
    const int g0 = t * 8;            // chain 0 output start
    const int g1 = (L / 2) + t * 8;  // chain 1 output start (4096 % pairlen == 0)

    const int pb0 = (g0 / pairlen) * pairlen, o0 = g0 & (pairlen - 1);
    const int pb1 = (g1 / pairlen) * pairlen, o1 = g1 & (pairlen - 1);

    // partition searches (independent -> overlapped latency)
    int alo0 = o0 - R; if (alo0 < 0) alo0 = 0;
    int ahi0 = (o0 < R) ? o0 : R;
    int alo1 = o1 - R; if (alo1 < 0) alo1 = 0;
    int ahi1 = (o1 < R) ? o1 : R;
    while (alo0 < ahi0 || alo1 < ahi1) {
        if (alo0 < ahi0) {
            int amid = (alo0 + ahi0) >> 1;
            if (src[PAD(pb0 + amid)] <= src[PAD(pb0 + R + o0 - 1 - amid)])
                alo0 = amid + 1; else ahi0 = amid;
        }
        if (alo1 < ahi1) {
            int amid = (alo1 + ahi1) >> 1;
            if (src[PAD(pb1 + amid)] <= src[PAD(pb1 + R + o1 - 1 - amid)])
                alo1 = amid + 1; else ahi1 = amid;
        }
    }
    int a0 = alo0, b0 = o0 - alo0;
    int a1 = alo1, b1 = o1 - alo1;

    float av0 = (a0 < R) ? src[PAD(pb0 + a0)]     : FLT_MAX;
    float bv0 = (b0 < R) ? src[PAD(pb0 + R + b0)] : FLT_MAX;
    float av1 = (a1 < R) ? src[PAD(pb1 + a1)]     : FLT_MAX;
    float bv1 = (b1 < R) ? src[PAD(pb1 + R + b1)] : FLT_MAX;
#pragma unroll
    for (int i = 0; i < 8; ++i) {
        bool tA0 = (a0 < R) && (b0 >= R || av0 <= bv0);
        bool tA1 = (a1 < R) && (b1 >= R || av1 <= bv1);
        float ov0 = tA0 ? av0 : bv0;
        float ov1 = tA1 ? av1 : bv1;
        if (tA0) { ++a0; av0 = (a0 < R) ? src[PAD(pb0 + a0)]     : FLT_MAX; }
        else     { ++b0; bv0 = (b0 < R) ? src[PAD(pb0 + R + b0)] : FLT_MAX; }
        if (tA1) { ++a1; av1 = (a1 < R) ? src[PAD(pb1 + a1)]     : FLT_MAX; }
        else     { ++b1; bv1 = (b1 < R) ? src[PAD(pb1 + R + b1)] : FLT_MAX; }
        dst[PAD(g0 + i)] = ov0;
        dst[PAD(g1 + i)] = ov1;
    }
}

// k-th smallest (0-indexed) of the union of two sorted runs in the same padded
// buffer at bases Ab, Bb, each length n.
__device__ __forceinline__ float select2(const float* __restrict__ buf,
                                         int Ab, int Bb, int n, int k)
{
    int ilo = (k + 1 - n > 0) ? (k + 1 - n) : 0;
    int ihi = (k + 1 < n) ? (k + 1) : n;
    for (;;) {
        int i = (ilo + ihi) >> 1;
        int j = k + 1 - i;
        float Aim1 = (i > 0) ? buf[PAD(Ab + i - 1)] : -FLT_MAX;
        float Ai   = (i < n) ? buf[PAD(Ab + i)]     :  FLT_MAX;
        float Bjm1 = (j > 0) ? buf[PAD(Bb + j - 1)] : -FLT_MAX;
        float Bj   = (j < n) ? buf[PAD(Bb + j)]     :  FLT_MAX;
        if (Aim1 > Bj)       ihi = i - 1;
        else if (Bjm1 > Ai)  ilo = i + 1;
        else return fmaxf(Aim1, Bjm1);
    }
}

__global__ __launch_bounds__(NT, 2) void mtf_kernel(const float* __restrict__ x,
                                                    float* __restrict__ out)
{
    extern __shared__ char smem_raw[];
    float*    bufA = reinterpret_cast<float*>(smem_raw);
    float*    bufB = reinterpret_cast<float*>(smem_raw + BUF_BYTES);
    unsigned* hist = reinterpret_cast<unsigned*>(smem_raw + 2 * BUF_BYTES);

    __shared__ float s_eytz[128];    // BFS layout of 127 padded edges
    __shared__ int   s_wmin[16], s_wmax[16], s_wneg[16];
    __shared__ int   s_m, s_neg;

    const int row  = blockIdx.x;
    const int t    = threadIdx.x;
    const int w    = t >> 5;
    const int lane = t & 31;

    const float* __restrict__ xr = x + (size_t)row * L;
    const float4* __restrict__ xr4 = reinterpret_cast<const float4*>(xr);

    // ---- Phase 1: load raw row, per-thread scan (registers only) ----
    float v[IPT];
    int lmin = L, lmax = -1, lneg = 0;
#pragma unroll
    for (int j = 0; j < 4; ++j) {
        float4 p = xr4[t * 4 + j];
        int base = t * IPT + j * 4;
        v[j * 4 + 0] = p.x; v[j * 4 + 1] = p.y;
        v[j * 4 + 2] = p.z; v[j * 4 + 3] = p.w;
#pragma unroll
        for (int c = 0; c < 4; ++c) {
            float val = v[j * 4 + c];
            int idx = base + c;
            if (val != 0.0f) { if (idx < lmin) lmin = idx; if (idx > lmax) lmax = idx; }
            lneg += (val < 0.0f) ? 1 : 0;
        }
    }
    lmin = __reduce_min_sync(0xffffffffu, lmin);
    lmax = __reduce_max_sync(0xffffffffu, lmax);
    lneg = __reduce_add_sync(0xffffffffu, lneg);
    if (lane == 0) { s_wmin[w] = lmin; s_wmax[w] = lmax; s_wneg[w] = lneg; }

    // ---- Phase 2: bitonic sort RAW values (ALU/SHFL only, no mask pass) ----
    warp_bitonic_512(v, lane);
#pragma unroll
    for (int i = 0; i < IPT; ++i) bufA[PAD(t * IPT + i)] = v[i];   // conflict-free

    // hist zeroing in the shadow before the barrier
    for (int i = t; i < NB * NB; i += NT) hist[i] = 0u;

    __syncthreads();                             // SYNC 1

    // ---- Phase 3: warp 0 finalizes the scan while everyone merges ----
    if (w == 0 && lane < 16) {
        int a = s_wmin[lane], b = s_wmax[lane], c = s_wneg[lane];
        a = __reduce_min_sync(0x0000ffffu, a);
        b = __reduce_max_sync(0x0000ffffu, b);
        c = __reduce_add_sync(0x0000ffffu, c);
        if (lane == 0) {
            s_m   = (b >= 0) ? (b - a + 1) : 0;
            s_neg = c;
        }
    }

    // ---- Phase 4: three merge rounds: 512 -> 1024 -> 2048 -> 4096 ----
    merge_round<512>(bufA, bufB, t);  __syncthreads();   // SYNC 2
    merge_round<1024>(bufB, bufA, t); __syncthreads();   // SYNC 3
    merge_round<2048>(bufA, bufB, t); __syncthreads();   // SYNC 4
    // two sorted runs of 4096 at padded bases 0 and 4096 in bufB

    // ---- Phase 5: Eytzinger nodes select their edge directly.
    // masked[k] = raw_sorted[k] if k < neg_count else raw_sorted[k + zout]
    if (t >= 1 && t < 128) {
        int d    = 31 - __clz((unsigned)t);
        int idx0 = ((((t - (1 << d)) << 1) + 1) << (6 - d)) - 1;   // in-order index
        float q = FLT_MAX;
        if (idx0 < NB) {
            int m = s_m;
            if (m > 0) {
                const float step = 1.0f / 65.0f;
                float qlev = (float)idx0 * step;
                float pos  = qlev * (float)(m - 1);
                int   lo   = (int)floorf(pos);
                int   hi   = (int)ceilf(pos);
                float frac = pos - (float)lo;
                int neg = s_neg, zout = L - m;
                int klo = (lo < neg) ? lo : lo + zout;
                int khi = (hi < neg) ? hi : hi + zout;
                float vlo = select2(bufB, 0, 4096, 4096, klo);
                float vhi = (khi == klo) ? vlo
                                         : select2(bufB, 0, 4096, 4096, khi);
                q = vlo + frac * (vhi - vlo);
            } else {
                q = 0.0f;
            }
        }
        s_eytz[t] = q;
    }
    __syncthreads();                             // SYNC 5

    // ---- Phase 6: bin all values (conflict-free Eytzinger, L1-hot reload) ----
    int binreg[IPT];
#pragma unroll
    for (int j = 0; j < 4; ++j) {
        float4 p = xr4[t * 4 + j];
        float vals[4] = {p.x, p.y, p.z, p.w};
#pragma unroll
        for (int c = 0; c < 4; ++c) {
            float val = vals[c];
            unsigned node = 1;
#pragma unroll
            for (int s = 0; s < 7; ++s)
                node = 2u * node + (s_eytz[node] <= val ? 1u : 0u);
            int b = (int)node - 128;             // count of edges <= val
            binreg[j * 4 + c] = (b > NB - 1) ? (NB - 1) : b;
        }
    }

    // boundary bin (next thread's first element) without smem/barrier
    int nextbin = __shfl_down_sync(0xffffffffu, binreg[0], 1);
    if (lane == 31 && t < NT - 1) {
        float val = xr[t * IPT + IPT];           // L1-hot scalar load
        unsigned node = 1;
#pragma unroll
        for (int s = 0; s < 7; ++s)
            node = 2u * node + (s_eytz[node] <= val ? 1u : 0u);
        int b = (int)node - 128;
        nextbin = (b > NB - 1) ? (NB - 1) : b;
    }

    // ---- Phase 7: transition histogram (shared atomics) ----
#pragma unroll
    for (int i = 0; i < IPT - 1; ++i)
        atomicAdd(&hist[binreg[i] * NB + binreg[i + 1]], 1u);
    if (t < NT - 1)
        atomicAdd(&hist[binreg[IPT - 1] * NB + nextbin], 1u);
    __syncthreads();                             // SYNC 6

    // ---- Phase 8: normalize + store ----
    const float inv = 1.0f / (float)(L - 1);
    float* __restrict__ outr = out + (size_t)row * NB * NB;
    for (int i = t; i < NB * NB; i += NT)
        outr[i] = (float)hist[i] * inv;
}

extern "C" void kernel_launch(void* const* d_in, const int* in_sizes, int n_in,
                              void* d_out, int out_size)
{
    const float* x = (const float*)d_in[0];
    float* out = (float*)d_out;
    const int rows = in_sizes[0] / L;   // 512*4 = 2048

    cudaFuncSetAttribute(mtf_kernel,
                         cudaFuncAttributeMaxDynamicSharedMemorySize,
                         (int)SMEM_TOTAL);
    mtf_kernel<<<rows, NT, SMEM_TOTAL>>>(x, out);
}